// round 1
// baseline (speedup 1.0000x reference)
#include <cuda_runtime.h>
#include <cuda_bf16.h>
#include <cstdint>

#define B_    4
#define GX_   480
#define GY_   360
#define CIN_  64
#define COUT_ 32
#define NSEG  (B_ * GX_ * GY_)          // 691200
#define NPT   480000

// Scratch: encoded-max grid [NSEG][64] as monotonic uint32.
// enc(f) for finite f is always >= 0x00800000, so init value 0 == "empty / -inf".
__device__ unsigned int g_grid[(size_t)NSEG * CIN_];

__device__ __forceinline__ unsigned int enc_f32(float f) {
    unsigned int u = __float_as_uint(f);
    return (u & 0x80000000u) ? ~u : (u | 0x80000000u);
}
__device__ __forceinline__ float dec_f32(unsigned int u) {
    return (u & 0x80000000u) ? __uint_as_float(u ^ 0x80000000u)
                             : __uint_as_float(~u);
}

// ---------------- Kernel 1: init grid to 0 (empty encoding) ----------------
__global__ void init_grid_kernel() {
    // NSEG*64 u32 = 11,059,200 uint4
    size_t i = (size_t)blockIdx.x * blockDim.x + threadIdx.x;
    const size_t n4 = (size_t)NSEG * CIN_ / 4;
    uint4 z = make_uint4(0u, 0u, 0u, 0u);
    if (i < n4) reinterpret_cast<uint4*>(g_grid)[i] = z;
}

// ---------------- Kernel 2: warp-per-point atomic segment max --------------
__global__ void scatter_max_kernel(const float* __restrict__ fea,
                                   const int*   __restrict__ ind,
                                   const int*   __restrict__ bidx) {
    int warpId = (blockIdx.x * blockDim.x + threadIdx.x) >> 5;
    int lane   = threadIdx.x & 31;
    if (warpId >= NPT) return;
    int x = ind[2 * warpId];
    int y = ind[2 * warpId + 1];
    int b = bidx[warpId];
    size_t seg = (size_t)b * (GX_ * GY_) + (size_t)x * GY_ + y;

    // 64 channels per point: float2 per lane -> fully coalesced 512B row read
    float2 v = reinterpret_cast<const float2*>(fea + (size_t)warpId * CIN_)[lane];
    unsigned int* dst = g_grid + seg * CIN_ + 2 * lane;
    atomicMax(dst,     enc_f32(v.x));
    atomicMax(dst + 1, enc_f32(v.y));
}

// ---------------- Kernel 3: decode + Linear(64->32) + ReLU + transpose -----
// 128 voxels per block; stage pool rows via shared (padded transpose),
// W/b in shared; empty voxels skip FMA and emit zeros.
__global__ __launch_bounds__(128) void gemm_epilogue_kernel(
        const float* __restrict__ W,      // [64][32] row-major
        const float* __restrict__ bias,   // [32]
        float* __restrict__ out)          // [B][32][GX][GY]
{
    __shared__ float sPool[128 * 65];
    __shared__ float sW[CIN_ * COUT_];
    __shared__ float sB[COUT_];
    __shared__ unsigned char sEmpty[128];

    const int tid = threadIdx.x;
    const size_t base = (size_t)blockIdx.x * 128;   // first voxel of this block

    // stage W (2048 floats) + bias
    #pragma unroll
    for (int i = tid; i < CIN_ * COUT_; i += 128) sW[i] = W[i];
    if (tid < COUT_) sB[tid] = bias[tid];

    // stage 128 voxel rows (8192 u32), coalesced, decode on the fly
    const unsigned int* gBase = g_grid + base * CIN_;
    #pragma unroll
    for (int k = 0; k < 64; k++) {
        int i = k * 128 + tid;
        unsigned int u = gBase[i];
        int vloc = i >> 6;
        int ch   = i & 63;
        sPool[vloc * 65 + ch] = dec_f32(u);
        if (ch == 0) sEmpty[vloc] = (u == 0u);
    }
    __syncthreads();

    const size_t v   = base + tid;
    const int    bi  = (int)(v / (GX_ * GY_));
    const int    rem = (int)(v % (GX_ * GY_));
    const int    x   = rem / GY_;
    const int    y   = rem % GY_;
    // out[((bi*32+co)*GX + x)*GY + y]; consecutive tid -> consecutive y -> coalesced
    float* optr = out + (((size_t)bi * COUT_) * GX_ + x) * GY_ + y;
    const size_t coStride = (size_t)GX_ * GY_;

    if (sEmpty[tid]) {
        #pragma unroll
        for (int co = 0; co < COUT_; co++) optr[co * coStride] = 0.0f;
        return;
    }

    float acc[COUT_];
    #pragma unroll
    for (int co = 0; co < COUT_; co++) acc[co] = sB[co];

    const float* myRow = &sPool[tid * 65];
    #pragma unroll 4
    for (int c = 0; c < CIN_; c++) {
        float pv = myRow[c];
        const float4* w4 = reinterpret_cast<const float4*>(&sW[c * COUT_]);
        #pragma unroll
        for (int j = 0; j < 8; j++) {
            float4 w = w4[j];
            acc[4 * j + 0] = fmaf(pv, w.x, acc[4 * j + 0]);
            acc[4 * j + 1] = fmaf(pv, w.y, acc[4 * j + 1]);
            acc[4 * j + 2] = fmaf(pv, w.z, acc[4 * j + 2]);
            acc[4 * j + 3] = fmaf(pv, w.w, acc[4 * j + 3]);
        }
    }
    #pragma unroll
    for (int co = 0; co < COUT_; co++)
        optr[co * coStride] = fmaxf(acc[co], 0.0f);
}

extern "C" void kernel_launch(void* const* d_in, const int* in_sizes, int n_in,
                              void* d_out, int out_size) {
    const float* pt_fea   = (const float*)d_in[0];
    const int*   pt_ind   = (const int*)  d_in[1];
    const int*   batch_ix = (const int*)  d_in[2];
    const float* W_comp   = (const float*)d_in[3];
    const float* b_comp   = (const float*)d_in[4];
    float*       out      = (float*)d_out;

    // 1) init scratch (11,059,200 uint4)
    {
        const size_t n4 = (size_t)NSEG * CIN_ / 4;
        int threads = 256;
        int blocks  = (int)((n4 + threads - 1) / threads);
        init_grid_kernel<<<blocks, threads>>>();
    }
    // 2) scatter atomic max: warp per point
    {
        int threads = 256;                      // 8 warps/block
        int blocks  = (NPT + 7) / 8;            // 60000
        scatter_max_kernel<<<blocks, threads>>>(pt_fea, pt_ind, batch_ix);
    }
    // 3) GEMM + ReLU + transposed store
    {
        int blocks = NSEG / 128;                // 5400
        gemm_epilogue_kernel<<<blocks, 128>>>(W_comp, b_comp, out);
    }
}

// round 2
// speedup vs baseline: 1.3518x; 1.3518x over previous
#include <cuda_runtime.h>
#include <cuda_bf16.h>
#include <cstdint>

#define B_     4
#define GXF    480            // full output x
#define GXC    360            // compact x (pt_ind in [0,360))
#define GY_    360
#define CIN_   64
#define COUT_  32
#define NPT    480000
#define NVOX   (B_ * GXC * GY_)        // 518400 compact voxels
#define SCAN_BLK 1024
#define NB1    ((NVOX + SCAN_BLK - 1) / SCAN_BLK)   // 507

__device__ unsigned int d_cnt[NVOX];
__device__ unsigned int d_cursor[NVOX];
__device__ unsigned int d_blockSums[NB1];
__device__ unsigned int d_blockOff[NB1];
__device__ unsigned int d_seg[NPT];
__device__ unsigned int d_idx[NPT];
__device__ unsigned int d_segs[NPT];

__device__ __forceinline__ unsigned int enc_f32(float f) {
    unsigned int u = __float_as_uint(f);
    return (u & 0x80000000u) ? ~u : (u | 0x80000000u);
}
__device__ __forceinline__ float dec_f32(unsigned int u) {
    return (u & 0x80000000u) ? __uint_as_float(u ^ 0x80000000u)
                             : __uint_as_float(~u);
}

// -------- Z: zero counters --------
__global__ void zero_cnt_kernel() {
    int i = blockIdx.x * blockDim.x + threadIdx.x;      // uint4 index
    const int n4 = NVOX / 4;                            // 129600
    if (i < n4) reinterpret_cast<uint4*>(d_cnt)[i] = make_uint4(0u,0u,0u,0u);
}

// -------- A: seg id + histogram --------
__global__ void count_kernel(const int* __restrict__ ind,
                             const int* __restrict__ bidx) {
    int i = blockIdx.x * blockDim.x + threadIdx.x;
    if (i >= NPT) return;
    int2 xy = reinterpret_cast<const int2*>(ind)[i];
    int b = bidx[i];
    unsigned int s = (unsigned)((b * GXC + xy.x) * GY_ + xy.y);
    d_seg[i] = s;
    atomicAdd(&d_cnt[s], 1u);
}

// -------- B: block-wise exclusive scan --------
__global__ void scan_block_kernel(const unsigned int* __restrict__ in,
                                  unsigned int* __restrict__ out,
                                  unsigned int* bs, int n) {
    __shared__ unsigned int wsum[32];
    int tid = threadIdx.x, lane = tid & 31, wid = tid >> 5;
    int gid = blockIdx.x * SCAN_BLK + tid;
    unsigned int x = (gid < n) ? in[gid] : 0u;
    unsigned int inc = x;
    #pragma unroll
    for (int d = 1; d < 32; d <<= 1) {
        unsigned int v = __shfl_up_sync(0xFFFFFFFFu, inc, d);
        if (lane >= d) inc += v;
    }
    if (lane == 31) wsum[wid] = inc;
    __syncthreads();
    if (wid == 0) {
        unsigned int v = wsum[lane];
        #pragma unroll
        for (int d = 1; d < 32; d <<= 1) {
            unsigned int t = __shfl_up_sync(0xFFFFFFFFu, v, d);
            if (lane >= d) v += t;
        }
        wsum[lane] = v;
    }
    __syncthreads();
    unsigned int warpOff = (wid > 0) ? wsum[wid - 1] : 0u;
    if (gid < n) out[gid] = warpOff + inc - x;
    if (tid == SCAN_BLK - 1 && bs) bs[blockIdx.x] = warpOff + inc;
}

// -------- B3: add block offsets --------
__global__ void scan_add_kernel() {
    int gid = blockIdx.x * SCAN_BLK + threadIdx.x;
    if (gid < NVOX) d_cursor[gid] += d_blockOff[blockIdx.x];
}

// -------- C: scatter sorted ids (cursor -> per-voxel end) --------
__global__ void scatter_kernel() {
    int i = blockIdx.x * blockDim.x + threadIdx.x;
    if (i >= NPT) return;
    unsigned int s = d_seg[i];
    unsigned int pos = atomicAdd(&d_cursor[s], 1u);
    d_idx[pos]  = (unsigned)i;
    d_segs[pos] = s;
}

// -------- D: fused segment-max + Linear(64->32) + ReLU + transposed store --
__global__ __launch_bounds__(256) void fused_kernel(
        const float* __restrict__ fea,
        const float* __restrict__ W,
        const float* __restrict__ bias,
        float* __restrict__ out) {
    __shared__ unsigned int uPool[128 * 65];
    __shared__ float sW[CIN_ * COUT_];
    __shared__ float sB[COUT_];
    __shared__ int sS, sE;

    const int tid = threadIdx.x;
    const int base = blockIdx.x * 128;

    #pragma unroll
    for (int i = tid; i < CIN_ * COUT_; i += 256) sW[i] = W[i];
    if (tid < COUT_) sB[tid] = bias[tid];
    #pragma unroll
    for (int i = tid; i < 128 * 65; i += 256) uPool[i] = 0u;
    if (tid == 0) {
        unsigned int e = d_cursor[base + 127];
        unsigned int s = d_cursor[base] - d_cnt[base];
        sS = (int)s; sE = (int)e;
    }
    __syncthreads();

    // Phase 1: warp-per-point smem atomic max (points contiguous in [S,E))
    const int S = sS, E = sE;
    const int wid = tid >> 5, lane = tid & 31;
    for (int p = S + wid; p < E; p += 8) {
        int i     = (int)d_idx[p];
        int vloc  = (int)d_segs[p] - base;
        const float* row = fea + (size_t)i * CIN_;
        float a = row[lane];
        float b = row[lane + 32];
        atomicMax(&uPool[vloc * 65 + lane],      enc_f32(a));
        atomicMax(&uPool[vloc * 65 + 32 + lane], enc_f32(b));
    }
    __syncthreads();

    // Phase 2: 2 threads per voxel, 16 outputs each
    const int v    = tid & 127;
    const int half = tid >> 7;
    const int cv   = base + v;
    const int bi   = cv / (GXC * GY_);
    const int rem  = cv % (GXC * GY_);
    const int x    = rem / GY_;
    const int y    = rem % GY_;
    float* optr = out + (((size_t)bi * COUT_ + half * 16) * GXF + x) * GY_ + y;
    const size_t cs = (size_t)GXF * GY_;

    if (uPool[v * 65] == 0u) {       // empty voxel (all 64 ch written if any point)
        #pragma unroll
        for (int j = 0; j < 16; j++) optr[j * cs] = 0.0f;
        return;
    }
    float acc[16];
    #pragma unroll
    for (int j = 0; j < 16; j++) acc[j] = sB[half * 16 + j];

    const unsigned int* myRow = &uPool[v * 65];
    #pragma unroll 4
    for (int c = 0; c < CIN_; c++) {
        float pv = dec_f32(myRow[c]);
        const float4* w4 = reinterpret_cast<const float4*>(&sW[c * COUT_ + half * 16]);
        #pragma unroll
        for (int j = 0; j < 4; j++) {
            float4 w = w4[j];
            acc[4*j+0] = fmaf(pv, w.x, acc[4*j+0]);
            acc[4*j+1] = fmaf(pv, w.y, acc[4*j+1]);
            acc[4*j+2] = fmaf(pv, w.z, acc[4*j+2]);
            acc[4*j+3] = fmaf(pv, w.w, acc[4*j+3]);
        }
    }
    #pragma unroll
    for (int j = 0; j < 16; j++) optr[j * cs] = fmaxf(acc[j], 0.0f);
}

// -------- E: zero the x in [360,480) output band --------
__global__ void band_zero_kernel(float* __restrict__ out) {
    // per (b,co) chunk: 120*360 = 43200 floats = 10800 float4
    int g = blockIdx.x * blockDim.x + threadIdx.x;
    const int per = (GXF - GXC) * GY_ / 4;                 // 10800
    if (g >= B_ * COUT_ * per) return;
    int c   = g / per;                                      // b*32+co
    int off = g % per;
    float4* p = reinterpret_cast<float4*>(
        out + (size_t)c * GXF * GY_ + (size_t)GXC * GY_);
    p[off] = make_float4(0.f, 0.f, 0.f, 0.f);
}

extern "C" void kernel_launch(void* const* d_in, const int* in_sizes, int n_in,
                              void* d_out, int out_size) {
    const float* pt_fea   = (const float*)d_in[0];
    const int*   pt_ind   = (const int*)  d_in[1];
    const int*   batch_ix = (const int*)  d_in[2];
    const float* W_comp   = (const float*)d_in[3];
    const float* b_comp   = (const float*)d_in[4];
    float*       out      = (float*)d_out;

    unsigned int *p_cnt, *p_cursor, *p_bs, *p_boff;
    cudaGetSymbolAddress((void**)&p_cnt,    d_cnt);
    cudaGetSymbolAddress((void**)&p_cursor, d_cursor);
    cudaGetSymbolAddress((void**)&p_bs,     d_blockSums);
    cudaGetSymbolAddress((void**)&p_boff,   d_blockOff);

    zero_cnt_kernel<<<(NVOX/4 + 255)/256, 256>>>();
    count_kernel<<<(NPT + 255)/256, 256>>>(pt_ind, batch_ix);
    scan_block_kernel<<<NB1, SCAN_BLK>>>(p_cnt, p_cursor, p_bs, NVOX);
    scan_block_kernel<<<1,   SCAN_BLK>>>(p_bs,  p_boff, nullptr, NB1);
    scan_add_kernel<<<NB1, SCAN_BLK>>>();
    scatter_kernel<<<(NPT + 255)/256, 256>>>();
    band_zero_kernel<<<(B_*COUT_*10800 + 255)/256, 256>>>(out);
    fused_kernel<<<NVOX/128, 256>>>(pt_fea, W_comp, b_comp, out);
}